// round 9
// baseline (speedup 1.0000x reference)
#include <cuda_runtime.h>
#include <cstdint>

// Problem constants
#define BB     8
#define RR     2048
#define CC     4096
#define NROWS  (BB * RR)
#define WORDS  (CC / 32)
#define K_FRONT 1228u               // int(4096*0.30)
#define K_RAND  409u                // int(4096*0.10)

#define T1  512
#define EPT 8

// Front bracket: scores ~ N(0,1); q30 of 4096 in (-0.70, -0.35) w/ 8.5-sigma margin.
#define KLO  0x40CCCCCCu
#define FRNG 0x00800000u            // KHI - KLO = 2^23 exactly
#define PIV  (1u << 29)             // rand pivot: E[count]=512 >= 409

// Persistent fused kernel
#define NB      296                 // 2 blocks/SM x 148 SMs (fully resident)
#define NPAIRS  8192                // 8 b x 128 mt x 8 jpair

// Dynamic smem (words): [0,16384) tiles (overlays k1 hist 10496), [16384,+64) control
#define CTRL      16384
#define SMW_TOTAL (16384 + 64)
#define SMB_TOTAL (SMW_TOTAL * 4)   // 65792 bytes

// ---- scratch ----
__device__ uint32_t g_smask[NROWS * WORDS];   // student keep-bits, 8 MB
__device__ uint32_t g_front0[BB * WORDS];     // front bits for row 0 of each batch
__device__ uint32_t g_flags[NROWS];           // row-completion flags
__device__ uint32_t g_row_ctr;
__device__ uint32_t g_pair_ctr;

// ---- threefry2x32 round, both heavy ops steered to the fma pipe ----
__device__ __forceinline__ void tf_round(uint32_t& x0, uint32_t& x1,
                                         uint32_t rm, uint32_t m1) {
    x0 = x0 * m1 + x1;
    unsigned long long p = (unsigned long long)x1 * rm;
    x1 = ((uint32_t)p ^ (uint32_t)(p >> 32)) ^ x0;
}

// Left-aligned ordering key of jax.random.uniform at flat index g (low 9 bits 0).
__device__ __forceinline__ uint32_t rand_key(uint32_t g,
        uint32_t m13, uint32_t m15, uint32_t m26, uint32_t m6,
        uint32_t m17, uint32_t m29, uint32_t m16, uint32_t m24, uint32_t m1) {
    uint32_t x0 = 0u, x1 = g + 42u;
    tf_round(x0,x1,m13,m1); tf_round(x0,x1,m15,m1); tf_round(x0,x1,m26,m1); tf_round(x0,x1,m6,m1);
    x0 += 42u;          x1 += 0x1BD11BF1u;
    tf_round(x0,x1,m17,m1); tf_round(x0,x1,m29,m1); tf_round(x0,x1,m16,m1); tf_round(x0,x1,m24,m1);
    x0 += 0x1BD11BF0u;  x1 += 2u;
    tf_round(x0,x1,m13,m1); tf_round(x0,x1,m15,m1); tf_round(x0,x1,m26,m1); tf_round(x0,x1,m6,m1);
    x0 += 0u;           x1 += 45u;
    tf_round(x0,x1,m17,m1); tf_round(x0,x1,m29,m1); tf_round(x0,x1,m16,m1); tf_round(x0,x1,m24,m1);
    x0 += 42u;          x1 += 0x1BD11BF4u;
    tf_round(x0,x1,m13,m1); tf_round(x0,x1,m15,m1); tf_round(x0,x1,m26,m1); tf_round(x0,x1,m6,m1);
    x0 += 0x1BD11BF0u;  x1 += 5u;
    return (x0 ^ x1) & 0xFFFFFE00u;
}

__device__ __forceinline__ uint32_t warp_inscan(uint32_t v, int lane) {
#pragma unroll
    for (int d = 1; d < 32; d <<= 1) {
        uint32_t y = __shfl_up_sync(0xFFFFFFFFu, v, d);
        if (lane >= d) v += y;
    }
    return v;
}
__device__ __forceinline__ uint32_t warp_exscan(uint32_t v, int lane) {
    return warp_inscan(v, lane) - v;
}

// Exact full-range fallback: top-down 8-bit radix select (block-wide).
__device__ __noinline__ void radix8_fallback(const uint32_t (&key)[EPT], uint32_t K,
                                             int npass, int t, int lane,
                                             uint32_t* hist, uint32_t* s_ctl,
                                             uint32_t& T, uint32_t& need) {
    uint32_t prefix = 0, kk = K - 1;
    for (int p = 0; p < npass; p++) {
        const int shift = 24 - 8 * p;
        if (t < 256) hist[t] = 0;
        __syncthreads();
        for (int j = 0; j < EPT; j++) {
            uint32_t kv = key[j];
            bool m = (p == 0) || ((kv >> (shift + 8)) == prefix);
            if (m) atomicAdd(&hist[(kv >> shift) & 255u], 1u);
        }
        __syncthreads();
        if (t < 32) {
            uint32_t h[8], sum = 0;
            for (int b = 0; b < 8; b++) { h[b] = hist[8 * t + b]; sum += h[b]; }
            uint32_t run = warp_exscan(sum, lane);
            for (int b = 0; b < 8; b++) {
                if (kk >= run && kk < run + h[b]) {
                    s_ctl[0] = (uint32_t)(8 * t + b);
                    s_ctl[1] = kk - run;
                }
                run += h[b];
            }
        }
        __syncthreads();
        prefix = (prefix << 8) | s_ctl[0];
        kk = s_ctl[1];
        __syncthreads();
    }
    T = prefix << (32 - 8 * npass);
    need = kk + 1;
}

// ============================================================================
// Row task: R8's bracketed dual select with singleton-bin shortcut. Exact.
// ============================================================================
__device__ __forceinline__ void do_row(int q, const float* __restrict__ score,
        uint32_t* smem,
        uint32_t m13, uint32_t m15, uint32_t m26, uint32_t m6,
        uint32_t m17, uint32_t m29, uint32_t m16, uint32_t m24, uint32_t m1) {
    const int t = threadIdx.x;
    const int wi = t >> 5, lane = t & 31;
    const uint32_t lmask_lt = (1u << lane) - 1u;
    const float* row = score + (size_t)q * CC;

    uint32_t* hist    = smem;            // [0:4096) fp1 | [4096:8192) rp1 | [8192:10240) fp2 | [10240:10496) rp2
    uint32_t* s_warpA = smem + CTRL + 4;
    uint32_t* s_warpB = smem + CTRL + 20;
    uint32_t* s_ctl   = smem + CTRL + 36;
    uint32_t* s_cnt   = smem + CTRL + 44;
    uint32_t* s_val   = smem + CTRL + 46;
    uint32_t* s_bf = hist;               // tie overlays (dead hist region)
    uint32_t* s_br = hist + 128;
    uint32_t* s_pf = hist + 256;
    uint32_t* s_pr = hist + 384;

    // ---- zero hist + ctl ----
    {
        uint4* h4 = (uint4*)hist;
        uint4 z = make_uint4(0, 0, 0, 0);
#pragma unroll
        for (int i = 0; i < 6; i++) {
            int idx = t + i * T1;
            if (idx < 2624) h4[idx] = z;
        }
    }
    if (t < 6) s_ctl[t] = 0;
    __syncthreads();

    // ---- prologue: keys + fused pass-1 hist + below-bracket count ----
    uint32_t skey[EPT], rkey[EPT];
    uint32_t cl = 0;
#pragma unroll
    for (int j = 0; j < EPT; j++) {
        int c = j * T1 + t;
        uint32_t u = __float_as_uint(row[c]);
        skey[j] = u ^ ((u & 0x80000000u) ? 0xFFFFFFFFu : 0x80000000u);
        rkey[j] = rand_key((uint32_t)(q * CC + c), m13,m15,m26,m6,m17,m29,m16,m24,m1);
        uint32_t d = skey[j] - KLO;
        if (d < FRNG) atomicAdd(&hist[d >> 11], 1u);
        if (rkey[j] < PIV) atomicAdd(&hist[4096u + (rkey[j] >> 17)], 1u);
        cl += __popc(__ballot_sync(0xFFFFFFFFu, skey[j] < KLO));
    }
    if (lane == 0) s_warpB[wi] = cl;
    __syncthreads();

    // ---- pass-1 gather + packed dual block-scan ----
    uint32_t hf[8], hr[8], fs = 0, rs = 0;
#pragma unroll
    for (int i = 0; i < 8; i++) { hf[i] = hist[8 * t + i];        fs += hf[i]; }
#pragma unroll
    for (int i = 0; i < 8; i++) { hr[i] = hist[4096 + 8 * t + i]; rs += hr[i]; }
    uint32_t v = fs | (rs << 16);
    uint32_t incl = warp_inscan(v, lane);
    if (lane == 31) s_warpA[wi] = incl;
    if (t == 0) {
        uint32_t s = 0;
#pragma unroll
        for (int i = 0; i < 16; i++) s += s_warpB[i];
        s_cnt[0] = s;
    }
    __syncthreads();
    if (wi == 0) {
        uint32_t wv = (lane < 16) ? s_warpA[lane] : 0u;
        uint32_t wincl = warp_inscan(wv, lane);
        if (lane < 16) s_warpA[lane] = wincl - wv;
        if (lane == 15) s_cnt[1] = wincl;       // grand totals (n_in | c0<<16)
    }
    __syncthreads();
    const uint32_t c_lo = s_cnt[0];
    const uint32_t n_in = s_cnt[1] & 0xFFFFu;
    const uint32_t c0   = s_cnt[1] >> 16;
    const uint32_t kfp  = K_FRONT - 1u - c_lo;  // wraps if bracket missed -> fallback
    const uint32_t krp  = K_RAND - 1u;
    {
        uint32_t base = (incl - v) + s_warpA[wi];
        uint32_t run = base & 0xFFFFu;
#pragma unroll
        for (int i = 0; i < 8; i++) {
            if (kfp >= run && kfp < run + hf[i]) {
                s_ctl[0] = (uint32_t)(8 * t + i);
                s_ctl[1] = kfp - run;
                s_ctl[4] = hf[i];
            }
            run += hf[i];
        }
        run = base >> 16;
#pragma unroll
        for (int i = 0; i < 8; i++) {
            if (krp >= run && krp < run + hr[i]) {
                s_ctl[2] = (uint32_t)(8 * t + i);
                s_ctl[3] = krp - run;
                s_ctl[5] = hr[i];
            }
            run += hr[i];
        }
    }
    __syncthreads();

    uint32_t Tf, need_f, Tr, need_r, cnt_f = 0, cnt_r = 0;
    const bool fast = (c_lo <= K_FRONT - 1u) &&
                      (K_FRONT - 1u < c_lo + n_in) &&
                      (c0 >= K_RAND);
    if (!fast) {
        radix8_fallback(skey, K_FRONT, 4, t, lane, hist, s_ctl, Tf, need_f);
        radix8_fallback(rkey, K_RAND, 3, t, lane, hist, s_ctl, Tr, need_r);
    } else {
        const uint32_t Bf = s_ctl[0], kf2 = s_ctl[1], cbf = s_ctl[4];
        const uint32_t Br = s_ctl[2], kr2 = s_ctl[3], cbr = s_ctl[5];
        const bool p2f = (cbf != 1u);
        const bool p2r = (cbr != 1u);

        // ---- combined singleton-write / pass-2 accumulate ----
#pragma unroll
        for (int j = 0; j < EPT; j++) {
            uint32_t d = skey[j] - KLO;
            if (d < FRNG && (d >> 11) == Bf) {
                if (p2f) atomicAdd(&hist[8192u + (d & 0x7FFu)], 1u);
                else     s_val[0] = skey[j];
            }
            if (rkey[j] < PIV && (rkey[j] >> 17) == Br) {
                if (p2r) atomicAdd(&hist[10240u + ((rkey[j] >> 9) & 0xFFu)], 1u);
                else     s_val[1] = rkey[j];
            }
        }
        __syncthreads();

        if (p2f || p2r) {
            uint32_t g2[4], f2 = 0;
#pragma unroll
            for (int i = 0; i < 4; i++) { g2[i] = hist[8192 + 4 * t + i]; f2 += g2[i]; }
            uint32_t r2 = (t < 256) ? hist[10240 + t] : 0u;
            uint32_t v2 = f2 | (r2 << 16);
            uint32_t incl2 = warp_inscan(v2, lane);
            if (lane == 31) s_warpA[wi] = incl2;
            __syncthreads();
            if (wi == 0) {
                uint32_t wv = (lane < 16) ? s_warpA[lane] : 0u;
                uint32_t wincl = warp_inscan(wv, lane);
                if (lane < 16) s_warpA[lane] = wincl - wv;
            }
            __syncthreads();
            uint32_t base2 = (incl2 - v2) + s_warpA[wi];
            if (p2f) {
                uint32_t run = base2 & 0xFFFFu;
#pragma unroll
                for (int i = 0; i < 4; i++) {
                    if (kf2 >= run && kf2 < run + g2[i]) {
                        s_ctl[0] = (uint32_t)(4 * t + i);
                        s_ctl[1] = kf2 - run;
                        s_ctl[4] = g2[i];
                    }
                    run += g2[i];
                }
            }
            if (p2r && t < 256) {
                uint32_t run = base2 >> 16;
                if (kr2 >= run && kr2 < run + r2) {
                    s_ctl[2] = (uint32_t)t;
                    s_ctl[3] = kr2 - run;
                    s_ctl[5] = r2;
                }
            }
        }
        __syncthreads();
        if (p2f) { Tf = KLO + (Bf << 11) + s_ctl[0]; need_f = s_ctl[1] + 1u; cnt_f = s_ctl[4]; }
        else     { Tf = s_val[0];                    need_f = 1u;            cnt_f = 1u; }
        if (p2r) { Tr = (Br << 17) + (s_ctl[2] << 9); need_r = s_ctl[3] + 1u; cnt_r = s_ctl[5]; }
        else     { Tr = s_val[1];                     need_r = 1u;            cnt_r = 1u; }
    }

    const bool is_row0 = ((q & (RR - 1)) == 0);
    const bool easy = (cnt_f == need_f) && (cnt_r == need_r);
    if (easy) {
#pragma unroll
        for (int j = 0; j < EPT; j++) {
            const int w = j * 16 + wi;
            bool fsel = skey[j] <= Tf;
            bool sel  = fsel || (rkey[j] <= Tr);
            uint32_t keep_w = __ballot_sync(0xFFFFFFFFu, !sel);
            if (lane == 0) g_smask[q * WORDS + w] = keep_w;
            if (is_row0) {
                uint32_t front_w = __ballot_sync(0xFFFFFFFFu, fsel);
                if (lane == 0) g_front0[(q >> 11) * WORDS + w] = front_w;
            }
        }
    } else {
        __syncthreads();   // hist region about to be overlaid by tie arrays
#pragma unroll
        for (int j = 0; j < EPT; j++) {
            uint32_t bfw = __ballot_sync(0xFFFFFFFFu, skey[j] == Tf);
            uint32_t brw = __ballot_sync(0xFFFFFFFFu, rkey[j] == Tr);
            if (lane == 0) { s_bf[j * 16 + wi] = bfw; s_br[j * 16 + wi] = brw; }
        }
        __syncthreads();
        if (t < 32) {
            uint32_t a[4], b[4], sa = 0, sb = 0;
#pragma unroll
            for (int i = 0; i < 4; i++) { a[i] = __popc(s_bf[4 * t + i]); sa += a[i];
                                          b[i] = __popc(s_br[4 * t + i]); sb += b[i]; }
            uint32_t ea = warp_exscan(sa, t), eb = warp_exscan(sb, t);
#pragma unroll
            for (int i = 0; i < 4; i++) {
                s_pf[4 * t + i] = ea; ea += a[i];
                s_pr[4 * t + i] = eb; eb += b[i];
            }
        }
        __syncthreads();
#pragma unroll
        for (int j = 0; j < EPT; j++) {
            const int w = j * 16 + wi;
            uint32_t bfw = s_bf[w], brw = s_br[w];
            bool fsel = (skey[j] < Tf) ||
                        ((skey[j] == Tf) && (s_pf[w] + __popc(bfw & lmask_lt) < need_f));
            bool rsel = (rkey[j] < Tr) ||
                        ((rkey[j] == Tr) && (s_pr[w] + __popc(brw & lmask_lt) < need_r));
            uint32_t keep_w  = __ballot_sync(0xFFFFFFFFu, !(fsel || rsel));
            uint32_t front_w = __ballot_sync(0xFFFFFFFFu, fsel);
            if (lane == 0) {
                g_smask[q * WORDS + w] = keep_w;
                if (is_row0) g_front0[(q >> 11) * WORDS + w] = front_w;
            }
        }
    }
}

// ============================================================================
// Pair task: two 32m x 128j transpose tiles (block halves). Masks via __ldcg.
// ============================================================================
__device__ __forceinline__ void do_pair(int pair, const float* __restrict__ score,
                                        float* __restrict__ out_s,
                                        float* __restrict__ out_t,
                                        uint32_t* smem) {
    const int h   = threadIdx.x >> 8;         // half 0/1
    const int t   = threadIdx.x & 255;
    const int lane = t & 31, wid = t >> 5;    // wid 0..7
    const int jp = pair & 7;
    const int mt = (pair >> 3) & 127;
    const int b  = pair >> 10;
    const int m0 = mt * 32;
    const int j0 = (2 * jp + h) * 128;

    float* ss = (float*)smem + h * 8192;      // 4096 words
    float* st = ss + 4096;

    const float* base = score + (size_t)b * (RR * CC);
#pragma unroll
    for (int k = 0; k < 4; k++) {
        const int mr = wid + 8 * k;           // 0..31
        const int m  = m0 + mr;
        const int j  = 4 * lane;
        const float4 v = *(const float4*)(base + (size_t)m * 2048 + j0 + j);
        const int r = m >> 1;
        const int c = ((m & 1) << 11) + j0 + j;
        const uint32_t sh = c & 31;
        const uint32_t mw = __ldcg(&g_smask[(b * RR + r) * WORDS + (c >> 5)]);
        float4 vs;
        vs.x = ((mw >> (sh + 0)) & 1u) ? v.x : 0.0f;
        vs.y = ((mw >> (sh + 1)) & 1u) ? v.y : 0.0f;
        vs.z = ((mw >> (sh + 2)) & 1u) ? v.z : 0.0f;
        vs.w = ((mw >> (sh + 3)) & 1u) ? v.w : 0.0f;
        float4 vt = v;
        if (r == 0) {
            const uint32_t fw = __ldcg(&g_front0[b * WORDS + (c >> 5)]);
            vt.x = ((fw >> (sh + 0)) & 1u) ? v.x : 0.0f;
            vt.y = ((fw >> (sh + 1)) & 1u) ? v.y : 0.0f;
            vt.z = ((fw >> (sh + 2)) & 1u) ? v.z : 0.0f;
            vt.w = ((fw >> (sh + 3)) & 1u) ? v.w : 0.0f;
        }
        const int col4 = lane ^ ((mr >> 2) & 7);
        *(float4*)&ss[mr * 128 + 4 * col4] = vs;
        *(float4*)&st[mr * 128 + 4 * col4] = vt;
    }
    __syncthreads();

    float* os = out_s + (size_t)b * (RR * CC);
    float* ot = out_t + (size_t)b * (RR * CC);
    const int qd = t & 7;
#pragma unroll
    for (int jj = 0; jj < 4; jj++) {
        const int jl = (t >> 3) + 32 * jj;
        const int cw = 4 * ((jl >> 2) ^ qd) + (jl & 3);
        float4 rs, rt;
        rs.x = ss[(4 * qd + 0) * 128 + cw];
        rs.y = ss[(4 * qd + 1) * 128 + cw];
        rs.z = ss[(4 * qd + 2) * 128 + cw];
        rs.w = ss[(4 * qd + 3) * 128 + cw];
        rt.x = st[(4 * qd + 0) * 128 + cw];
        rt.y = st[(4 * qd + 1) * 128 + cw];
        rt.z = st[(4 * qd + 2) * 128 + cw];
        rt.w = st[(4 * qd + 3) * 128 + cw];
        const size_t o = (size_t)(j0 + jl) * CC + m0 + 4 * qd;
        __stwt((float4*)(os + o), rs);
        __stwt((float4*)(ot + o), rt);
    }
    __syncthreads();   // smem reused by next task
}

// ============================================================================
__global__ void zero_kernel() {
    int i = blockIdx.x * blockDim.x + threadIdx.x;
    if (i < NROWS) g_flags[i] = 0u;
    if (i == 0) { g_row_ctr = 0u; g_pair_ctr = 0u; }
}

__global__ __launch_bounds__(T1, 2) void fused_kernel(
        const float* __restrict__ score, float* __restrict__ out_s,
        float* __restrict__ out_t,
        uint32_t m13, uint32_t m15, uint32_t m26, uint32_t m6,
        uint32_t m17, uint32_t m29, uint32_t m16, uint32_t m24, uint32_t m1) {
    extern __shared__ __align__(16) uint32_t smem[];
    uint32_t* s_work = smem + CTRL;          // [0]=queue broadcast, [1]=ready
    const int t = threadIdx.x;

    bool rows_left = true;
    bool havep = false;
    int mypair = 0;

    while (true) {
        // ---- one row (primary work; never blocks) ----
        if (rows_left) {
            if (t == 0) s_work[0] = atomicAdd(&g_row_ctr, 1u);
            __syncthreads();
            int q = (int)s_work[0];
            __syncthreads();
            if (q < NROWS) {
                do_row(q, score, smem, m13,m15,m26,m6,m17,m29,m16,m24,m1);
                __threadfence();             // release masks to gpu scope
                __syncthreads();
                if (t == 0) *(volatile uint32_t*)&g_flags[q] = 1u;
            } else {
                rows_left = false;
            }
        }
        // ---- acquire a pair if none held ----
        if (!havep) {
            if (t == 0) s_work[0] = atomicAdd(&g_pair_ctr, 1u);
            __syncthreads();
            mypair = (int)s_work[0];
            __syncthreads();
            havep = (mypair < NPAIRS);
        }
        // ---- attempt the held pair (non-blocking while rows remain) ----
        if (havep) {
            const int qb = (mypair >> 3) * 16;   // 16 required row flags
            bool ready;
            do {
                uint32_t f = 1u;
                if (t < 16) f = *(volatile uint32_t*)&g_flags[qb + t];
                uint32_t bal = __ballot_sync(0xFFFFFFFFu, f != 0u);
                if (t == 0) s_work[1] = (bal == 0xFFFFFFFFu) ? 1u : 0u;
                __syncthreads();
                ready = (s_work[1] != 0u);
                __syncthreads();
                if (!ready && !rows_left) __nanosleep(200);
            } while (!ready && !rows_left);
            if (ready) {
                __threadfence();             // acquire before reading masks
                do_pair(mypair, score, out_s, out_t, smem);
                havep = false;
            }
        }
        if (!rows_left && !havep) break;
    }
}

// ============================================================================
extern "C" void kernel_launch(void* const* d_in, const int* in_sizes, int n_in,
                              void* d_out, int out_size) {
    const float* score = (const float*)d_in[0];
    float* out = (float*)d_out;
    float* out_teacher = out + (size_t)BB * RR * CC;

    cudaFuncSetAttribute(fused_kernel, cudaFuncAttributeMaxDynamicSharedMemorySize,
                         SMB_TOTAL);

    zero_kernel<<<(NROWS + T1 - 1) / T1, T1>>>();
    fused_kernel<<<NB, T1, SMB_TOTAL>>>(score, out, out_teacher,
        1u << 13, 1u << 15, 1u << 26, 1u << 6,
        1u << 17, 1u << 29, 1u << 16, 1u << 24, 1u);
}

// round 12
// speedup vs baseline: 1.1729x; 1.1729x over previous
#include <cuda_runtime.h>
#include <cstdint>

// Problem constants
#define BB     8
#define RR     2048
#define CC     4096
#define NROWS  (BB * RR)
#define WORDS  (CC / 32)
#define K_FRONT 1228u               // int(4096*0.30)
#define K_RAND  409u                // int(4096*0.10)

#define T1  512
#define EPT 8

// Front bracket: scores ~ N(0,1); q30 of 4096 in (-0.70, -0.35) w/ 8.5-sigma margin.
#define KLO  0x40CCCCCCu
#define FRNG 0x00800000u            // KHI - KLO = 2^23 exactly
#define PIV  (1u << 29)             // rand pivot: E[count]=512 >= 409

// ---- scratch ----
__device__ uint32_t g_smask[NROWS * WORDS];   // student keep-bits, 8 MB
__device__ uint32_t g_front0[BB * WORDS];     // front bits for row 0 of each batch

// ---- threefry2x32 round, both heavy ops steered to the fma pipe ----
// x0 update as IMAD (m1==1 at runtime) -> fma; rotl via wide multiply by 2^r
// (runtime multiplier) -> fma; combine folds to a single LOP3 on alu.
__device__ __forceinline__ void tf_round(uint32_t& x0, uint32_t& x1,
                                         uint32_t rm, uint32_t m1) {
    x0 = x0 * m1 + x1;
    unsigned long long p = (unsigned long long)x1 * rm;
    x1 = ((uint32_t)p ^ (uint32_t)(p >> 32)) ^ x0;
}

// Left-aligned ordering key of jax.random.uniform at flat index g (low 9 bits 0).
// key=(0,42): ks=[0,42,0x1BD11BF0].
__device__ __forceinline__ uint32_t rand_key(uint32_t g,
        uint32_t m13, uint32_t m15, uint32_t m26, uint32_t m6,
        uint32_t m17, uint32_t m29, uint32_t m16, uint32_t m24, uint32_t m1) {
    uint32_t x0 = 0u, x1 = g + 42u;
    tf_round(x0,x1,m13,m1); tf_round(x0,x1,m15,m1); tf_round(x0,x1,m26,m1); tf_round(x0,x1,m6,m1);
    x0 += 42u;          x1 += 0x1BD11BF1u;
    tf_round(x0,x1,m17,m1); tf_round(x0,x1,m29,m1); tf_round(x0,x1,m16,m1); tf_round(x0,x1,m24,m1);
    x0 += 0x1BD11BF0u;  x1 += 2u;
    tf_round(x0,x1,m13,m1); tf_round(x0,x1,m15,m1); tf_round(x0,x1,m26,m1); tf_round(x0,x1,m6,m1);
    x0 += 0u;           x1 += 45u;
    tf_round(x0,x1,m17,m1); tf_round(x0,x1,m29,m1); tf_round(x0,x1,m16,m1); tf_round(x0,x1,m24,m1);
    x0 += 42u;          x1 += 0x1BD11BF4u;
    tf_round(x0,x1,m13,m1); tf_round(x0,x1,m15,m1); tf_round(x0,x1,m26,m1); tf_round(x0,x1,m6,m1);
    x0 += 0x1BD11BF0u;  x1 += 5u;
    return (x0 ^ x1) & 0xFFFFFE00u;
}

__device__ __forceinline__ uint32_t warp_inscan(uint32_t v, int lane) {
#pragma unroll
    for (int d = 1; d < 32; d <<= 1) {
        uint32_t y = __shfl_up_sync(0xFFFFFFFFu, v, d);
        if (lane >= d) v += y;
    }
    return v;
}
__device__ __forceinline__ uint32_t warp_exscan(uint32_t v, int lane) {
    return warp_inscan(v, lane) - v;
}

__global__ void noop_kernel() {}

// Exact full-range fallback: top-down 8-bit radix select (block-wide).
__device__ __noinline__ void radix8_fallback(const uint32_t (&key)[EPT], uint32_t K,
                                             int npass, int t, int lane,
                                             uint32_t* hist, uint32_t* s_ctl,
                                             uint32_t& T, uint32_t& need) {
    uint32_t prefix = 0, kk = K - 1;
    for (int p = 0; p < npass; p++) {
        const int shift = 24 - 8 * p;
        if (t < 256) hist[t] = 0;
        __syncthreads();
        for (int j = 0; j < EPT; j++) {
            uint32_t kv = key[j];
            bool m = (p == 0) || ((kv >> (shift + 8)) == prefix);
            if (m) atomicAdd(&hist[(kv >> shift) & 255u], 1u);
        }
        __syncthreads();
        if (t < 32) {
            uint32_t h[8], sum = 0;
            for (int b = 0; b < 8; b++) { h[b] = hist[8 * t + b]; sum += h[b]; }
            uint32_t run = warp_exscan(sum, lane);
            for (int b = 0; b < 8; b++) {
                if (kk >= run && kk < run + h[b]) {
                    s_ctl[0] = (uint32_t)(8 * t + b);
                    s_ctl[1] = kk - run;
                }
                run += h[b];
            }
        }
        __syncthreads();
        prefix = (prefix << 8) | s_ctl[0];
        kk = s_ctl[1];
        __syncthreads();
    }
    T = prefix << (32 - 8 * npass);
    need = kk + 1;
}

// ============================================================================
// Kernel 1: bracketed dual select with singleton-bin shortcut and guarded
// locate loops (only the bin-owning thread's warp pays the locate cost).
// Exact & stable everywhere; full fallback retained.
// ============================================================================
__global__ __launch_bounds__(T1, 2) void k1_select(const float* __restrict__ score,
        uint32_t m13, uint32_t m15, uint32_t m26, uint32_t m6,
        uint32_t m17, uint32_t m29, uint32_t m16, uint32_t m24, uint32_t m1) {
    const int q = blockIdx.x;
    const int t = threadIdx.x;
    const int wi = t >> 5, lane = t & 31;
    const uint32_t lmask_lt = (1u << lane) - 1u;
    const float* row = score + (size_t)q * CC;

    // [0:4096) front p1 | [4096:8192) rand p1 | [8192:10240) front p2 | [10240:10496) rand p2
    __shared__ __align__(16) uint32_t hist[10496];
    __shared__ uint32_t s_warpA[16], s_warpB[16];
    __shared__ uint32_t s_ctl[6];
    __shared__ uint32_t s_cnt[2];
    __shared__ uint32_t s_val[2];      // singleton-bin threshold values
    // tie arrays overlay the (dead-by-then) hist region
    uint32_t* s_bf = hist;             // 128
    uint32_t* s_br = hist + 128;       // 128
    uint32_t* s_pf = hist + 256;       // 128
    uint32_t* s_pr = hist + 384;       // 128

    // ---- zero hist + ctl ----
    {
        uint4* h4 = (uint4*)hist;
        uint4 z = make_uint4(0, 0, 0, 0);
#pragma unroll
        for (int i = 0; i < 6; i++) {
            int idx = t + i * T1;
            if (idx < 2624) h4[idx] = z;
        }
    }
    if (t < 6) s_ctl[t] = 0;
    __syncthreads();

    // ---- prologue: keys + fused pass-1 hist + below-bracket count ----
    uint32_t skey[EPT], rkey[EPT];
    uint32_t cl = 0;
#pragma unroll
    for (int j = 0; j < EPT; j++) {
        int c = j * T1 + t;
        uint32_t u = __float_as_uint(row[c]);
        skey[j] = u ^ ((u & 0x80000000u) ? 0xFFFFFFFFu : 0x80000000u);
        rkey[j] = rand_key((uint32_t)(q * CC + c), m13,m15,m26,m6,m17,m29,m16,m24,m1);
        uint32_t d = skey[j] - KLO;
        if (d < FRNG) atomicAdd(&hist[d >> 11], 1u);
        if (rkey[j] < PIV) atomicAdd(&hist[4096u + (rkey[j] >> 17)], 1u);
        cl += __popc(__ballot_sync(0xFFFFFFFFu, skey[j] < KLO));
    }
    if (lane == 0) s_warpB[wi] = cl;
    __syncthreads();

    // ---- pass-1 gather + packed dual block-scan (totals fall out free) ----
    uint32_t hf[8], hr[8], fs = 0, rs = 0;
#pragma unroll
    for (int i = 0; i < 8; i++) { hf[i] = hist[8 * t + i];        fs += hf[i]; }
#pragma unroll
    for (int i = 0; i < 8; i++) { hr[i] = hist[4096 + 8 * t + i]; rs += hr[i]; }
    uint32_t v = fs | (rs << 16);
    uint32_t incl = warp_inscan(v, lane);
    if (lane == 31) s_warpA[wi] = incl;
    if (t == 0) {
        uint32_t s = 0;
#pragma unroll
        for (int i = 0; i < 16; i++) s += s_warpB[i];
        s_cnt[0] = s;
    }
    __syncthreads();
    if (wi == 0) {
        uint32_t wv = (lane < 16) ? s_warpA[lane] : 0u;
        uint32_t wincl = warp_inscan(wv, lane);
        if (lane < 16) s_warpA[lane] = wincl - wv;
        if (lane == 15) s_cnt[1] = wincl;       // grand totals (n_in | c0<<16)
    }
    __syncthreads();
    const uint32_t c_lo = s_cnt[0];
    const uint32_t n_in = s_cnt[1] & 0xFFFFu;
    const uint32_t c0   = s_cnt[1] >> 16;
    const uint32_t kfp  = K_FRONT - 1u - c_lo;  // wraps if bracket missed -> fallback
    const uint32_t krp  = K_RAND - 1u;
    {
        uint32_t base = (incl - v) + s_warpA[wi];
        uint32_t run = base & 0xFFFFu;
        if (kfp - run < fs) {                   // guarded: only owning thread's warp pays
#pragma unroll
            for (int i = 0; i < 8; i++) {
                if (kfp >= run && kfp < run + hf[i]) {
                    s_ctl[0] = (uint32_t)(8 * t + i);
                    s_ctl[1] = kfp - run;
                    s_ctl[4] = hf[i];           // threshold-bin population
                }
                run += hf[i];
            }
        }
        run = base >> 16;
        if (krp - run < rs) {
#pragma unroll
            for (int i = 0; i < 8; i++) {
                if (krp >= run && krp < run + hr[i]) {
                    s_ctl[2] = (uint32_t)(8 * t + i);
                    s_ctl[3] = krp - run;
                    s_ctl[5] = hr[i];
                }
                run += hr[i];
            }
        }
    }
    __syncthreads();

    uint32_t Tf, need_f, Tr, need_r, cnt_f = 0, cnt_r = 0;
    const bool fast = (c_lo <= K_FRONT - 1u) &&
                      (K_FRONT - 1u < c_lo + n_in) &&
                      (c0 >= K_RAND);
    if (!fast) {
        radix8_fallback(skey, K_FRONT, 4, t, lane, hist, s_ctl, Tf, need_f);
        radix8_fallback(rkey, K_RAND, 3, t, lane, hist, s_ctl, Tr, need_r);
    } else {
        const uint32_t Bf = s_ctl[0], kf2 = s_ctl[1], cbf = s_ctl[4];
        const uint32_t Br = s_ctl[2], kr2 = s_ctl[3], cbr = s_ctl[5];
        const bool p2f = (cbf != 1u);      // need pass-2 to resolve within-bin rank?
        const bool p2r = (cbr != 1u);

        // ---- combined singleton-write / pass-2 accumulate ----
#pragma unroll
        for (int j = 0; j < EPT; j++) {
            uint32_t d = skey[j] - KLO;
            if (d < FRNG && (d >> 11) == Bf) {
                if (p2f) atomicAdd(&hist[8192u + (d & 0x7FFu)], 1u);
                else     s_val[0] = skey[j];   // unique in-bin element = threshold
            }
            if (rkey[j] < PIV && (rkey[j] >> 17) == Br) {
                if (p2r) atomicAdd(&hist[10240u + ((rkey[j] >> 9) & 0xFFu)], 1u);
                else     s_val[1] = rkey[j];
            }
        }
        __syncthreads();

        if (p2f || p2r) {
            // ---- pass-2 scan & locate (predicated per select, guarded) ----
            uint32_t g2[4], f2 = 0;
#pragma unroll
            for (int i = 0; i < 4; i++) { g2[i] = hist[8192 + 4 * t + i]; f2 += g2[i]; }
            uint32_t r2 = (t < 256) ? hist[10240 + t] : 0u;
            uint32_t v2 = f2 | (r2 << 16);
            uint32_t incl2 = warp_inscan(v2, lane);
            if (lane == 31) s_warpA[wi] = incl2;
            __syncthreads();
            if (wi == 0) {
                uint32_t wv = (lane < 16) ? s_warpA[lane] : 0u;
                uint32_t wincl = warp_inscan(wv, lane);
                if (lane < 16) s_warpA[lane] = wincl - wv;
            }
            __syncthreads();
            uint32_t base2 = (incl2 - v2) + s_warpA[wi];
            if (p2f) {
                uint32_t run = base2 & 0xFFFFu;
                if (kf2 - run < f2) {
#pragma unroll
                    for (int i = 0; i < 4; i++) {
                        if (kf2 >= run && kf2 < run + g2[i]) {
                            s_ctl[0] = (uint32_t)(4 * t + i);
                            s_ctl[1] = kf2 - run;
                            s_ctl[4] = g2[i];
                        }
                        run += g2[i];
                    }
                }
            }
            if (p2r && t < 256) {
                uint32_t run = base2 >> 16;
                if (kr2 >= run && kr2 < run + r2) {
                    s_ctl[2] = (uint32_t)t;
                    s_ctl[3] = kr2 - run;
                    s_ctl[5] = r2;
                }
            }
        }
        __syncthreads();
        if (p2f) { Tf = KLO + (Bf << 11) + s_ctl[0]; need_f = s_ctl[1] + 1u; cnt_f = s_ctl[4]; }
        else     { Tf = s_val[0];                    need_f = 1u;            cnt_f = 1u; }
        if (p2r) { Tr = (Br << 17) + (s_ctl[2] << 9); need_r = s_ctl[3] + 1u; cnt_r = s_ctl[5]; }
        else     { Tr = s_val[1];                     need_r = 1u;            cnt_r = 1u; }
    }

    const bool is_row0 = ((q & (RR - 1)) == 0);
    const bool easy = (cnt_f == need_f) && (cnt_r == need_r);
    if (easy) {
        // all threshold-tied elements accepted -> pure <= comparisons
#pragma unroll
        for (int j = 0; j < EPT; j++) {
            const int w = j * 16 + wi;
            bool fsel = skey[j] <= Tf;
            bool sel  = fsel || (rkey[j] <= Tr);
            uint32_t keep_w = __ballot_sync(0xFFFFFFFFu, !sel);
            if (lane == 0) g_smask[q * WORDS + w] = keep_w;
            if (is_row0) {
                uint32_t front_w = __ballot_sync(0xFFFFFFFFu, fsel);
                if (lane == 0) g_front0[(q >> 11) * WORDS + w] = front_w;
            }
        }
    } else {
        // exact stable tie-break (rare): ballots cached, word-prefix scan
        __syncthreads();   // hist region about to be overlaid by tie arrays
#pragma unroll
        for (int j = 0; j < EPT; j++) {
            uint32_t bfw = __ballot_sync(0xFFFFFFFFu, skey[j] == Tf);
            uint32_t brw = __ballot_sync(0xFFFFFFFFu, rkey[j] == Tr);
            if (lane == 0) { s_bf[j * 16 + wi] = bfw; s_br[j * 16 + wi] = brw; }
        }
        __syncthreads();
        if (t < 32) {
            uint32_t a[4], b[4], sa = 0, sb = 0;
#pragma unroll
            for (int i = 0; i < 4; i++) { a[i] = __popc(s_bf[4 * t + i]); sa += a[i];
                                          b[i] = __popc(s_br[4 * t + i]); sb += b[i]; }
            uint32_t ea = warp_exscan(sa, t), eb = warp_exscan(sb, t);
#pragma unroll
            for (int i = 0; i < 4; i++) {
                s_pf[4 * t + i] = ea; ea += a[i];
                s_pr[4 * t + i] = eb; eb += b[i];
            }
        }
        __syncthreads();
#pragma unroll
        for (int j = 0; j < EPT; j++) {
            const int w = j * 16 + wi;
            uint32_t bfw = s_bf[w], brw = s_br[w];
            bool fsel = (skey[j] < Tf) ||
                        ((skey[j] == Tf) && (s_pf[w] + __popc(bfw & lmask_lt) < need_f));
            bool rsel = (rkey[j] < Tr) ||
                        ((rkey[j] == Tr) && (s_pr[w] + __popc(brw & lmask_lt) < need_r));
            uint32_t keep_w  = __ballot_sync(0xFFFFFFFFu, !(fsel || rsel));
            uint32_t front_w = __ballot_sync(0xFFFFFFFFu, fsel);
            if (lane == 0) {
                g_smask[q * WORDS + w] = keep_w;
                if (is_row0) g_front0[(q >> 11) * WORDS + w] = front_w;
            }
        }
    }
}

// ============================================================================
// Kernel 2: per-batch [4096 x 2048] transpose with mask application.
// Tile: 32 m-rows x 128 j-cols, float4 both sides, XOR-swizzled smem,
// streaming loads (__ldcs) + streaming stores (__stwt).
// ============================================================================
#define TJ 128
#define TM 32
__global__ __launch_bounds__(256) void k2_transpose(const float* __restrict__ score,
                                                    float* __restrict__ out_s,
                                                    float* __restrict__ out_t) {
    __shared__ float ss[TM * TJ];
    __shared__ float st[TM * TJ];
    const int b  = blockIdx.z;
    const int m0 = blockIdx.y * TM;
    const int j0 = blockIdx.x * TJ;
    const int t  = threadIdx.x;
    const int lane = t & 31, wid = t >> 5;

    const float* base = score + (size_t)b * (RR * CC);
#pragma unroll
    for (int k = 0; k < 4; k++) {
        const int mr = wid + 8 * k;
        const int m  = m0 + mr;
        const int j  = 4 * lane;
        const float4 v = __ldcs((const float4*)(base + (size_t)m * 2048 + j0 + j));
        const int r = m >> 1;
        const int c = ((m & 1) << 11) + j0 + j;
        const uint32_t sh = c & 31;
        const uint32_t mw = g_smask[(b * RR + r) * WORDS + (c >> 5)];
        float4 vs;
        vs.x = ((mw >> (sh + 0)) & 1u) ? v.x : 0.0f;
        vs.y = ((mw >> (sh + 1)) & 1u) ? v.y : 0.0f;
        vs.z = ((mw >> (sh + 2)) & 1u) ? v.z : 0.0f;
        vs.w = ((mw >> (sh + 3)) & 1u) ? v.w : 0.0f;
        float4 vt = v;
        if (r == 0) {
            const uint32_t fw = g_front0[b * WORDS + (c >> 5)];
            vt.x = ((fw >> (sh + 0)) & 1u) ? v.x : 0.0f;
            vt.y = ((fw >> (sh + 1)) & 1u) ? v.y : 0.0f;
            vt.z = ((fw >> (sh + 2)) & 1u) ? v.z : 0.0f;
            vt.w = ((fw >> (sh + 3)) & 1u) ? v.w : 0.0f;
        }
        const int col4 = lane ^ ((mr >> 2) & 7);
        *(float4*)&ss[mr * TJ + 4 * col4] = vs;
        *(float4*)&st[mr * TJ + 4 * col4] = vt;
    }
    __syncthreads();

    float* os = out_s + (size_t)b * (RR * CC);
    float* ot = out_t + (size_t)b * (RR * CC);
    const int qd = t & 7;
#pragma unroll
    for (int jj = 0; jj < 4; jj++) {
        const int jl = (t >> 3) + 32 * jj;
        const int cw = 4 * ((jl >> 2) ^ qd) + (jl & 3);
        float4 rs, rt;
        rs.x = ss[(4 * qd + 0) * TJ + cw];
        rs.y = ss[(4 * qd + 1) * TJ + cw];
        rs.z = ss[(4 * qd + 2) * TJ + cw];
        rs.w = ss[(4 * qd + 3) * TJ + cw];
        rt.x = st[(4 * qd + 0) * TJ + cw];
        rt.y = st[(4 * qd + 1) * TJ + cw];
        rt.z = st[(4 * qd + 2) * TJ + cw];
        rt.w = st[(4 * qd + 3) * TJ + cw];
        const size_t o = (size_t)(j0 + jl) * CC + m0 + 4 * qd;
        __stwt((float4*)(os + o), rs);     // streaming: don't pollute L2
        __stwt((float4*)(ot + o), rt);
    }
}

// ============================================================================
extern "C" void kernel_launch(void* const* d_in, const int* in_sizes, int n_in,
                              void* d_out, int out_size) {
    const float* score = (const float*)d_in[0];
    float* out = (float*)d_out;
    float* out_teacher = out + (size_t)BB * RR * CC;

    // runtime multipliers keep the wide-mul rotations / IMAD adds un-foldable
    k1_select<<<NROWS, T1>>>(score,
        1u << 13, 1u << 15, 1u << 26, 1u << 6,
        1u << 17, 1u << 29, 1u << 16, 1u << 24, 1u);

    dim3 grid(CC / 2 / TJ, CC / TM, BB);
    k2_transpose<<<grid, 256>>>(score, out, out_teacher);
    noop_kernel<<<1, 1>>>();
}

// round 14
// speedup vs baseline: 1.1803x; 1.0062x over previous
#include <cuda_runtime.h>
#include <cstdint>

// Problem constants
#define BB     8
#define RR     2048
#define CC     4096
#define NROWS  (BB * RR)
#define WORDS  (CC / 32)
#define K_FRONT 1228u               // int(4096*0.30)
#define K_RAND  409u                // int(4096*0.10)

#define T1  512
#define EPT 8

// Front bracket: scores ~ N(0,1); q30 of 4096 in (-0.70, -0.35) w/ 8.5-sigma margin.
#define KLO  0x40CCCCCCu
#define FRNG 0x00800000u            // KHI - KLO = 2^23 exactly
#define BELOW_THR 0xBF333334u       // d >= this  <=>  skey < KLO (unsigned wrap)
#define PIV  (1u << 29)             // rand pivot: E[count]=512 >= 409

// ---- scratch ----
__device__ uint32_t g_smask[NROWS * WORDS];   // student keep-bits, 8 MB
__device__ uint32_t g_front0[BB * WORDS];     // front bits for row 0 of each batch

// ---- threefry2x32 rounds, heavy ops steered to the fma pipe ----
// x0 update as IMAD (m1==1 at runtime) -> fma; rotl via wide multiply by 2^r
// (runtime multiplier) -> fma; combine folds to a single LOP3 on alu.
__device__ __forceinline__ void tf_round(uint32_t& x0, uint32_t& x1,
                                         uint32_t rm, uint32_t m1) {
    x0 = x0 * m1 + x1;
    unsigned long long p = (unsigned long long)x1 * rm;
    x1 = ((uint32_t)p ^ (uint32_t)(p >> 32)) ^ x0;
}
// Round with folded key-schedule add on x0: x0 = x0 + ks + x1 is one IADD3.
// (Caller must add x1's schedule constant BEFORE calling, as x1 feeds the mul.)
__device__ __forceinline__ void tf_round_ks(uint32_t& x0, uint32_t& x1,
                                            uint32_t rm, uint32_t ks) {
    x0 = x0 + ks + x1;
    unsigned long long p = (unsigned long long)x1 * rm;
    x1 = ((uint32_t)p ^ (uint32_t)(p >> 32)) ^ x0;
}

// Left-aligned ordering key of jax.random.uniform at flat index g (low 9 bits 0).
// key=(0,42): ks=[0,42,0x1BD11BF0]. Exactly 20 rounds, 5 injections, with the
// three non-zero mid-schedule x0-adds folded into the following round's IADD3:
//   r1-4(13,15,26,6) | +ks1/ks2+1 | r5-8(17,29,16,24) | +ks2/ks0+2 |
//   r9-12(13,15,26,6) | +ks0/ks1+3 | r13-16(17,29,16,24) | +ks1/ks2+4 |
//   r17-20(13,15,26,6) | +ks2/ks0+5
__device__ __forceinline__ uint32_t rand_key(uint32_t g,
        uint32_t m13, uint32_t m15, uint32_t m26, uint32_t m6,
        uint32_t m17, uint32_t m29, uint32_t m16, uint32_t m24, uint32_t m1) {
    uint32_t x0 = 0u, x1 = g + 42u;
    // rounds 1-4
    tf_round(x0,x1,m13,m1); tf_round(x0,x1,m15,m1); tf_round(x0,x1,m26,m1); tf_round(x0,x1,m6,m1);
    // inject: x0+=42 (folded into round 5), x1+=ks2+1
    x1 += 0x1BD11BF1u;
    tf_round_ks(x0,x1,m17,42u);                                   // round 5
    tf_round(x0,x1,m29,m1); tf_round(x0,x1,m16,m1); tf_round(x0,x1,m24,m1);  // 6-8
    // inject: x0+=ks2 (folded into round 9), x1+=ks0+2
    x1 += 2u;
    tf_round_ks(x0,x1,m13,0x1BD11BF0u);                           // round 9
    tf_round(x0,x1,m15,m1); tf_round(x0,x1,m26,m1); tf_round(x0,x1,m6,m1);   // 10-12
    // inject: x0+=ks0=0 (nothing), x1+=ks1+3
    x1 += 45u;
    tf_round(x0,x1,m17,m1); tf_round(x0,x1,m29,m1);               // 13-14
    tf_round(x0,x1,m16,m1); tf_round(x0,x1,m24,m1);               // 15-16
    // inject: x0+=42 (folded into round 17), x1+=ks2+4
    x1 += 0x1BD11BF4u;
    tf_round_ks(x0,x1,m13,42u);                                   // round 17
    tf_round(x0,x1,m15,m1); tf_round(x0,x1,m26,m1); tf_round(x0,x1,m6,m1);   // 18-20
    // final inject
    x0 += 0x1BD11BF0u;  x1 += 5u;
    return (x0 ^ x1) & 0xFFFFFE00u;
}

__device__ __forceinline__ uint32_t warp_inscan(uint32_t v, int lane) {
#pragma unroll
    for (int d = 1; d < 32; d <<= 1) {
        uint32_t y = __shfl_up_sync(0xFFFFFFFFu, v, d);
        if (lane >= d) v += y;
    }
    return v;
}
__device__ __forceinline__ uint32_t warp_exscan(uint32_t v, int lane) {
    return warp_inscan(v, lane) - v;
}

__global__ void noop_kernel() {}

// Exact full-range fallback: top-down 8-bit radix select (block-wide).
__device__ __noinline__ void radix8_fallback(const uint32_t (&key)[EPT], uint32_t K,
                                             int npass, int t, int lane,
                                             uint32_t* hist, uint32_t* s_ctl,
                                             uint32_t& T, uint32_t& need) {
    uint32_t prefix = 0, kk = K - 1;
    for (int p = 0; p < npass; p++) {
        const int shift = 24 - 8 * p;
        if (t < 256) hist[t] = 0;
        __syncthreads();
        for (int j = 0; j < EPT; j++) {
            uint32_t kv = key[j];
            bool m = (p == 0) || ((kv >> (shift + 8)) == prefix);
            if (m) atomicAdd(&hist[(kv >> shift) & 255u], 1u);
        }
        __syncthreads();
        if (t < 32) {
            uint32_t h[8], sum = 0;
            for (int b = 0; b < 8; b++) { h[b] = hist[8 * t + b]; sum += h[b]; }
            uint32_t run = warp_exscan(sum, lane);
            for (int b = 0; b < 8; b++) {
                if (kk >= run && kk < run + h[b]) {
                    s_ctl[0] = (uint32_t)(8 * t + b);
                    s_ctl[1] = kk - run;
                }
                run += h[b];
            }
        }
        __syncthreads();
        prefix = (prefix << 8) | s_ctl[0];
        kk = s_ctl[1];
        __syncthreads();
    }
    T = prefix << (32 - 8 * npass);
    need = kk + 1;
}

// ============================================================================
// Kernel 1: bracketed dual select with singleton-bin shortcut, guarded locate
// loops, folded threefry schedule, REDUX below-count, LDS.128 gathers.
// Exact & stable everywhere; full fallback retained.
// ============================================================================
__global__ __launch_bounds__(T1, 2) void k1_select(const float* __restrict__ score,
        uint32_t m13, uint32_t m15, uint32_t m26, uint32_t m6,
        uint32_t m17, uint32_t m29, uint32_t m16, uint32_t m24, uint32_t m1) {
    const int q = blockIdx.x;
    const int t = threadIdx.x;
    const int wi = t >> 5, lane = t & 31;
    const uint32_t lmask_lt = (1u << lane) - 1u;
    const float* row = score + (size_t)q * CC;

    // [0:4096) front p1 | [4096:8192) rand p1 | [8192:10240) front p2 | [10240:10496) rand p2
    __shared__ __align__(16) uint32_t hist[10496];
    __shared__ uint32_t s_warpA[16], s_warpB[16];
    __shared__ uint32_t s_ctl[6];
    __shared__ uint32_t s_cnt[2];
    __shared__ uint32_t s_val[2];      // singleton-bin threshold values
    // tie arrays overlay the (dead-by-then) hist region
    uint32_t* s_bf = hist;             // 128
    uint32_t* s_br = hist + 128;       // 128
    uint32_t* s_pf = hist + 256;       // 128
    uint32_t* s_pr = hist + 384;       // 128

    // ---- zero hist + ctl ----
    {
        uint4* h4 = (uint4*)hist;
        uint4 z = make_uint4(0, 0, 0, 0);
#pragma unroll
        for (int i = 0; i < 6; i++) {
            int idx = t + i * T1;
            if (idx < 2624) h4[idx] = z;
        }
    }
    if (t < 6) s_ctl[t] = 0;
    __syncthreads();

    // ---- prologue: keys + fused pass-1 hist + below-bracket count ----
    uint32_t skey[EPT], rkey[EPT];
    uint32_t cl = 0;
#pragma unroll
    for (int j = 0; j < EPT; j++) {
        int c = j * T1 + t;
        uint32_t u = __float_as_uint(row[c]);
        skey[j] = u ^ ((u & 0x80000000u) ? 0xFFFFFFFFu : 0x80000000u);
        rkey[j] = rand_key((uint32_t)(q * CC + c), m13,m15,m26,m6,m17,m29,m16,m24,m1);
        uint32_t d = skey[j] - KLO;
        if (d < FRNG) atomicAdd(&hist[d >> 11], 1u);
        if (rkey[j] < PIV) atomicAdd(&hist[4096u + (rkey[j] >> 17)], 1u);
        cl += (d >= BELOW_THR) ? 1u : 0u;       // skey < KLO (no ballot needed)
    }
    cl = __reduce_add_sync(0xFFFFFFFFu, cl);
    if (lane == 0) s_warpB[wi] = cl;
    __syncthreads();

    // ---- pass-1 gather (LDS.128) + packed dual block-scan ----
    uint32_t hf[8], hr[8], fs = 0, rs = 0;
    {
        uint4 a0 = *(uint4*)&hist[8 * t];
        uint4 a1 = *(uint4*)&hist[8 * t + 4];
        hf[0]=a0.x; hf[1]=a0.y; hf[2]=a0.z; hf[3]=a0.w;
        hf[4]=a1.x; hf[5]=a1.y; hf[6]=a1.z; hf[7]=a1.w;
        uint4 b0 = *(uint4*)&hist[4096 + 8 * t];
        uint4 b1 = *(uint4*)&hist[4096 + 8 * t + 4];
        hr[0]=b0.x; hr[1]=b0.y; hr[2]=b0.z; hr[3]=b0.w;
        hr[4]=b1.x; hr[5]=b1.y; hr[6]=b1.z; hr[7]=b1.w;
    }
#pragma unroll
    for (int i = 0; i < 8; i++) { fs += hf[i]; rs += hr[i]; }
    uint32_t v = fs | (rs << 16);
    uint32_t incl = warp_inscan(v, lane);
    if (lane == 31) s_warpA[wi] = incl;
    if (t == 0) {
        uint32_t s = 0;
#pragma unroll
        for (int i = 0; i < 16; i++) s += s_warpB[i];
        s_cnt[0] = s;
    }
    __syncthreads();
    if (wi == 0) {
        uint32_t wv = (lane < 16) ? s_warpA[lane] : 0u;
        uint32_t wincl = warp_inscan(wv, lane);
        if (lane < 16) s_warpA[lane] = wincl - wv;
        if (lane == 15) s_cnt[1] = wincl;       // grand totals (n_in | c0<<16)
    }
    __syncthreads();
    const uint32_t c_lo = s_cnt[0];
    const uint32_t n_in = s_cnt[1] & 0xFFFFu;
    const uint32_t c0   = s_cnt[1] >> 16;
    const uint32_t kfp  = K_FRONT - 1u - c_lo;  // wraps if bracket missed -> fallback
    const uint32_t krp  = K_RAND - 1u;
    {
        uint32_t base = (incl - v) + s_warpA[wi];
        uint32_t run = base & 0xFFFFu;
        if (kfp - run < fs) {                   // guarded: only owning thread's warp pays
#pragma unroll
            for (int i = 0; i < 8; i++) {
                if (kfp >= run && kfp < run + hf[i]) {
                    s_ctl[0] = (uint32_t)(8 * t + i);
                    s_ctl[1] = kfp - run;
                    s_ctl[4] = hf[i];           // threshold-bin population
                }
                run += hf[i];
            }
        }
        run = base >> 16;
        if (krp - run < rs) {
#pragma unroll
            for (int i = 0; i < 8; i++) {
                if (krp >= run && krp < run + hr[i]) {
                    s_ctl[2] = (uint32_t)(8 * t + i);
                    s_ctl[3] = krp - run;
                    s_ctl[5] = hr[i];
                }
                run += hr[i];
            }
        }
    }
    __syncthreads();

    uint32_t Tf, need_f, Tr, need_r, cnt_f = 0, cnt_r = 0;
    const bool fast = (c_lo <= K_FRONT - 1u) &&
                      (K_FRONT - 1u < c_lo + n_in) &&
                      (c0 >= K_RAND);
    if (!fast) {
        radix8_fallback(skey, K_FRONT, 4, t, lane, hist, s_ctl, Tf, need_f);
        radix8_fallback(rkey, K_RAND, 3, t, lane, hist, s_ctl, Tr, need_r);
    } else {
        const uint32_t Bf = s_ctl[0], kf2 = s_ctl[1], cbf = s_ctl[4];
        const uint32_t Br = s_ctl[2], kr2 = s_ctl[3], cbr = s_ctl[5];
        const bool p2f = (cbf != 1u);      // need pass-2 to resolve within-bin rank?
        const bool p2r = (cbr != 1u);

        // ---- combined singleton-write / pass-2 accumulate ----
#pragma unroll
        for (int j = 0; j < EPT; j++) {
            uint32_t d = skey[j] - KLO;
            if (d < FRNG && (d >> 11) == Bf) {
                if (p2f) atomicAdd(&hist[8192u + (d & 0x7FFu)], 1u);
                else     s_val[0] = skey[j];   // unique in-bin element = threshold
            }
            if (rkey[j] < PIV && (rkey[j] >> 17) == Br) {
                if (p2r) atomicAdd(&hist[10240u + ((rkey[j] >> 9) & 0xFFu)], 1u);
                else     s_val[1] = rkey[j];
            }
        }
        __syncthreads();

        if (p2f || p2r) {
            // ---- pass-2 scan & locate (predicated per select, guarded) ----
            uint32_t g2[4], f2 = 0;
            {
                uint4 c4 = *(uint4*)&hist[8192 + 4 * t];
                g2[0]=c4.x; g2[1]=c4.y; g2[2]=c4.z; g2[3]=c4.w;
            }
#pragma unroll
            for (int i = 0; i < 4; i++) f2 += g2[i];
            uint32_t r2 = (t < 256) ? hist[10240 + t] : 0u;
            uint32_t v2 = f2 | (r2 << 16);
            uint32_t incl2 = warp_inscan(v2, lane);
            if (lane == 31) s_warpA[wi] = incl2;
            __syncthreads();
            if (wi == 0) {
                uint32_t wv = (lane < 16) ? s_warpA[lane] : 0u;
                uint32_t wincl = warp_inscan(wv, lane);
                if (lane < 16) s_warpA[lane] = wincl - wv;
            }
            __syncthreads();
            uint32_t base2 = (incl2 - v2) + s_warpA[wi];
            if (p2f) {
                uint32_t run = base2 & 0xFFFFu;
                if (kf2 - run < f2) {
#pragma unroll
                    for (int i = 0; i < 4; i++) {
                        if (kf2 >= run && kf2 < run + g2[i]) {
                            s_ctl[0] = (uint32_t)(4 * t + i);
                            s_ctl[1] = kf2 - run;
                            s_ctl[4] = g2[i];
                        }
                        run += g2[i];
                    }
                }
            }
            if (p2r && t < 256) {
                uint32_t run = base2 >> 16;
                if (kr2 >= run && kr2 < run + r2) {
                    s_ctl[2] = (uint32_t)t;
                    s_ctl[3] = kr2 - run;
                    s_ctl[5] = r2;
                }
            }
        }
        __syncthreads();
        if (p2f) { Tf = KLO + (Bf << 11) + s_ctl[0]; need_f = s_ctl[1] + 1u; cnt_f = s_ctl[4]; }
        else     { Tf = s_val[0];                    need_f = 1u;            cnt_f = 1u; }
        if (p2r) { Tr = (Br << 17) + (s_ctl[2] << 9); need_r = s_ctl[3] + 1u; cnt_r = s_ctl[5]; }
        else     { Tr = s_val[1];                     need_r = 1u;            cnt_r = 1u; }
    }

    const bool is_row0 = ((q & (RR - 1)) == 0);
    const bool easy = (cnt_f == need_f) && (cnt_r == need_r);
    if (easy) {
        // all threshold-tied elements accepted -> pure <= comparisons
#pragma unroll
        for (int j = 0; j < EPT; j++) {
            const int w = j * 16 + wi;
            bool fsel = skey[j] <= Tf;
            bool sel  = fsel || (rkey[j] <= Tr);
            uint32_t keep_w = __ballot_sync(0xFFFFFFFFu, !sel);
            if (lane == 0) g_smask[q * WORDS + w] = keep_w;
            if (is_row0) {
                uint32_t front_w = __ballot_sync(0xFFFFFFFFu, fsel);
                if (lane == 0) g_front0[(q >> 11) * WORDS + w] = front_w;
            }
        }
    } else {
        // exact stable tie-break (rare): ballots cached, word-prefix scan
        __syncthreads();   // hist region about to be overlaid by tie arrays
#pragma unroll
        for (int j = 0; j < EPT; j++) {
            uint32_t bfw = __ballot_sync(0xFFFFFFFFu, skey[j] == Tf);
            uint32_t brw = __ballot_sync(0xFFFFFFFFu, rkey[j] == Tr);
            if (lane == 0) { s_bf[j * 16 + wi] = bfw; s_br[j * 16 + wi] = brw; }
        }
        __syncthreads();
        if (t < 32) {
            uint32_t a[4], b[4], sa = 0, sb = 0;
#pragma unroll
            for (int i = 0; i < 4; i++) { a[i] = __popc(s_bf[4 * t + i]); sa += a[i];
                                          b[i] = __popc(s_br[4 * t + i]); sb += b[i]; }
            uint32_t ea = warp_exscan(sa, t), eb = warp_exscan(sb, t);
#pragma unroll
            for (int i = 0; i < 4; i++) {
                s_pf[4 * t + i] = ea; ea += a[i];
                s_pr[4 * t + i] = eb; eb += b[i];
            }
        }
        __syncthreads();
#pragma unroll
        for (int j = 0; j < EPT; j++) {
            const int w = j * 16 + wi;
            uint32_t bfw = s_bf[w], brw = s_br[w];
            bool fsel = (skey[j] < Tf) ||
                        ((skey[j] == Tf) && (s_pf[w] + __popc(bfw & lmask_lt) < need_f));
            bool rsel = (rkey[j] < Tr) ||
                        ((rkey[j] == Tr) && (s_pr[w] + __popc(brw & lmask_lt) < need_r));
            uint32_t keep_w  = __ballot_sync(0xFFFFFFFFu, !(fsel || rsel));
            uint32_t front_w = __ballot_sync(0xFFFFFFFFu, fsel);
            if (lane == 0) {
                g_smask[q * WORDS + w] = keep_w;
                if (is_row0) g_front0[(q >> 11) * WORDS + w] = front_w;
            }
        }
    }
}

// ============================================================================
// Kernel 2: per-batch [4096 x 2048] transpose with mask application.
// Tile: 32 m-rows x 128 j-cols, float4 both sides, XOR-swizzled smem,
// streaming loads (__ldcs) + streaming stores (__stwt).
// ============================================================================
#define TJ 128
#define TM 32
__global__ __launch_bounds__(256) void k2_transpose(const float* __restrict__ score,
                                                    float* __restrict__ out_s,
                                                    float* __restrict__ out_t) {
    __shared__ float ss[TM * TJ];
    __shared__ float st[TM * TJ];
    const int b  = blockIdx.z;
    const int m0 = blockIdx.y * TM;
    const int j0 = blockIdx.x * TJ;
    const int t  = threadIdx.x;
    const int lane = t & 31, wid = t >> 5;

    const float* base = score + (size_t)b * (RR * CC);
#pragma unroll
    for (int k = 0; k < 4; k++) {
        const int mr = wid + 8 * k;
        const int m  = m0 + mr;
        const int j  = 4 * lane;
        const float4 v = __ldcs((const float4*)(base + (size_t)m * 2048 + j0 + j));
        const int r = m >> 1;
        const int c = ((m & 1) << 11) + j0 + j;
        const uint32_t sh = c & 31;
        const uint32_t mw = g_smask[(b * RR + r) * WORDS + (c >> 5)];
        float4 vs;
        vs.x = ((mw >> (sh + 0)) & 1u) ? v.x : 0.0f;
        vs.y = ((mw >> (sh + 1)) & 1u) ? v.y : 0.0f;
        vs.z = ((mw >> (sh + 2)) & 1u) ? v.z : 0.0f;
        vs.w = ((mw >> (sh + 3)) & 1u) ? v.w : 0.0f;
        float4 vt = v;
        if (r == 0) {
            const uint32_t fw = g_front0[b * WORDS + (c >> 5)];
            vt.x = ((fw >> (sh + 0)) & 1u) ? v.x : 0.0f;
            vt.y = ((fw >> (sh + 1)) & 1u) ? v.y : 0.0f;
            vt.z = ((fw >> (sh + 2)) & 1u) ? v.z : 0.0f;
            vt.w = ((fw >> (sh + 3)) & 1u) ? v.w : 0.0f;
        }
        const int col4 = lane ^ ((mr >> 2) & 7);
        *(float4*)&ss[mr * TJ + 4 * col4] = vs;
        *(float4*)&st[mr * TJ + 4 * col4] = vt;
    }
    __syncthreads();

    float* os = out_s + (size_t)b * (RR * CC);
    float* ot = out_t + (size_t)b * (RR * CC);
    const int qd = t & 7;
#pragma unroll
    for (int jj = 0; jj < 4; jj++) {
        const int jl = (t >> 3) + 32 * jj;
        const int cw = 4 * ((jl >> 2) ^ qd) + (jl & 3);
        float4 rs, rt;
        rs.x = ss[(4 * qd + 0) * TJ + cw];
        rs.y = ss[(4 * qd + 1) * TJ + cw];
        rs.z = ss[(4 * qd + 2) * TJ + cw];
        rs.w = ss[(4 * qd + 3) * TJ + cw];
        rt.x = st[(4 * qd + 0) * TJ + cw];
        rt.y = st[(4 * qd + 1) * TJ + cw];
        rt.z = st[(4 * qd + 2) * TJ + cw];
        rt.w = st[(4 * qd + 3) * TJ + cw];
        const size_t o = (size_t)(j0 + jl) * CC + m0 + 4 * qd;
        __stwt((float4*)(os + o), rs);     // streaming: don't pollute L2
        __stwt((float4*)(ot + o), rt);
    }
}

// ============================================================================
extern "C" void kernel_launch(void* const* d_in, const int* in_sizes, int n_in,
                              void* d_out, int out_size) {
    const float* score = (const float*)d_in[0];
    float* out = (float*)d_out;
    float* out_teacher = out + (size_t)BB * RR * CC;

    // runtime multipliers keep the wide-mul rotations / IMAD adds un-foldable
    k1_select<<<NROWS, T1>>>(score,
        1u << 13, 1u << 15, 1u << 26, 1u << 6,
        1u << 17, 1u << 29, 1u << 16, 1u << 24, 1u);

    dim3 grid(CC / 2 / TJ, CC / TM, BB);
    k2_transpose<<<grid, 256>>>(score, out, out_teacher);
    noop_kernel<<<1, 1>>>();
}

// round 15
// speedup vs baseline: 1.1836x; 1.0028x over previous
#include <cuda_runtime.h>
#include <cstdint>

// Problem constants
#define BB     8
#define RR     2048
#define CC     4096
#define NROWS  (BB * RR)
#define WORDS  (CC / 32)
#define K_FRONT 1228u               // int(4096*0.30)
#define K_RAND  409u                // int(4096*0.10)

#define T1  512
#define EPT 8

// Front bracket: scores ~ N(0,1); q30 of 4096 in (-0.70, -0.35) w/ 8.5-sigma margin.
#define KLO  0x40CCCCCCu
#define FRNG 0x00800000u            // KHI - KLO = 2^23 exactly
#define BELOW_THR 0xBF333334u       // d >= this  <=>  skey < KLO (unsigned wrap)
#define PIV  (1u << 29)             // rand pivot: E[count]=512 >= 409

// ---- scratch ----
__device__ uint32_t g_smask[NROWS * WORDS];   // student keep-bits, 8 MB
__device__ uint32_t g_front0[BB * WORDS];     // front bits for row 0 of each batch

// ---- threefry2x32 rounds, heavy ops steered to the fma pipe ----
__device__ __forceinline__ void tf_round(uint32_t& x0, uint32_t& x1,
                                         uint32_t rm, uint32_t m1) {
    x0 = x0 * m1 + x1;
    unsigned long long p = (unsigned long long)x1 * rm;
    x1 = ((uint32_t)p ^ (uint32_t)(p >> 32)) ^ x0;
}
__device__ __forceinline__ void tf_round_ks(uint32_t& x0, uint32_t& x1,
                                            uint32_t rm, uint32_t ks) {
    x0 = x0 + ks + x1;
    unsigned long long p = (unsigned long long)x1 * rm;
    x1 = ((uint32_t)p ^ (uint32_t)(p >> 32)) ^ x0;
}

// Left-aligned ordering key of jax.random.uniform at flat index g (low 9 bits 0).
// key=(0,42): ks=[0,42,0x1BD11BF0]. 20 rounds, 5 injections, x0-adds folded.
__device__ __forceinline__ uint32_t rand_key(uint32_t g,
        uint32_t m13, uint32_t m15, uint32_t m26, uint32_t m6,
        uint32_t m17, uint32_t m29, uint32_t m16, uint32_t m24, uint32_t m1) {
    uint32_t x0 = 0u, x1 = g + 42u;
    tf_round(x0,x1,m13,m1); tf_round(x0,x1,m15,m1); tf_round(x0,x1,m26,m1); tf_round(x0,x1,m6,m1);
    x1 += 0x1BD11BF1u;
    tf_round_ks(x0,x1,m17,42u);
    tf_round(x0,x1,m29,m1); tf_round(x0,x1,m16,m1); tf_round(x0,x1,m24,m1);
    x1 += 2u;
    tf_round_ks(x0,x1,m13,0x1BD11BF0u);
    tf_round(x0,x1,m15,m1); tf_round(x0,x1,m26,m1); tf_round(x0,x1,m6,m1);
    x1 += 45u;
    tf_round(x0,x1,m17,m1); tf_round(x0,x1,m29,m1);
    tf_round(x0,x1,m16,m1); tf_round(x0,x1,m24,m1);
    x1 += 0x1BD11BF4u;
    tf_round_ks(x0,x1,m13,42u);
    tf_round(x0,x1,m15,m1); tf_round(x0,x1,m26,m1); tf_round(x0,x1,m6,m1);
    x0 += 0x1BD11BF0u;  x1 += 5u;
    return (x0 ^ x1) & 0xFFFFFE00u;
}

__device__ __forceinline__ uint32_t warp_inscan(uint32_t v, int lane) {
#pragma unroll
    for (int d = 1; d < 32; d <<= 1) {
        uint32_t y = __shfl_up_sync(0xFFFFFFFFu, v, d);
        if (lane >= d) v += y;
    }
    return v;
}
__device__ __forceinline__ uint32_t warp_exscan(uint32_t v, int lane) {
    return warp_inscan(v, lane) - v;
}

__global__ void noop_kernel() {}

// Exact full-range fallback: top-down 8-bit radix select (block-wide).
__device__ __noinline__ void radix8_fallback(const uint32_t (&key)[EPT], uint32_t K,
                                             int npass, int t, int lane,
                                             uint32_t* hist, uint32_t* s_ctl,
                                             uint32_t& T, uint32_t& need) {
    uint32_t prefix = 0, kk = K - 1;
    for (int p = 0; p < npass; p++) {
        const int shift = 24 - 8 * p;
        if (t < 256) hist[t] = 0;
        __syncthreads();
        for (int j = 0; j < EPT; j++) {
            uint32_t kv = key[j];
            bool m = (p == 0) || ((kv >> (shift + 8)) == prefix);
            if (m) atomicAdd(&hist[(kv >> shift) & 255u], 1u);
        }
        __syncthreads();
        if (t < 32) {
            uint32_t h[8], sum = 0;
            for (int b = 0; b < 8; b++) { h[b] = hist[8 * t + b]; sum += h[b]; }
            uint32_t run = warp_exscan(sum, lane);
            for (int b = 0; b < 8; b++) {
                if (kk >= run && kk < run + h[b]) {
                    s_ctl[0] = (uint32_t)(8 * t + b);
                    s_ctl[1] = kk - run;
                }
                run += h[b];
            }
        }
        __syncthreads();
        prefix = (prefix << 8) | s_ctl[0];
        kk = s_ctl[1];
        __syncthreads();
    }
    T = prefix << (32 - 8 * npass);
    need = kk + 1;
}

// ============================================================================
// Kernel 1 (chunked by qoff): bracketed dual select, singleton-bin shortcut,
// guarded locate loops. Exact & stable everywhere; full fallback retained.
// ============================================================================
__global__ __launch_bounds__(T1, 2) void k1_select(const float* __restrict__ score,
        int qoff,
        uint32_t m13, uint32_t m15, uint32_t m26, uint32_t m6,
        uint32_t m17, uint32_t m29, uint32_t m16, uint32_t m24, uint32_t m1) {
    const int q = qoff + blockIdx.x;
    const int t = threadIdx.x;
    const int wi = t >> 5, lane = t & 31;
    const uint32_t lmask_lt = (1u << lane) - 1u;
    const float* row = score + (size_t)q * CC;

    __shared__ __align__(16) uint32_t hist[10496];
    __shared__ uint32_t s_warpA[16], s_warpB[16];
    __shared__ uint32_t s_ctl[6];
    __shared__ uint32_t s_cnt[2];
    __shared__ uint32_t s_val[2];
    uint32_t* s_bf = hist;
    uint32_t* s_br = hist + 128;
    uint32_t* s_pf = hist + 256;
    uint32_t* s_pr = hist + 384;

    {
        uint4* h4 = (uint4*)hist;
        uint4 z = make_uint4(0, 0, 0, 0);
#pragma unroll
        for (int i = 0; i < 6; i++) {
            int idx = t + i * T1;
            if (idx < 2624) h4[idx] = z;
        }
    }
    if (t < 6) s_ctl[t] = 0;
    __syncthreads();

    uint32_t skey[EPT], rkey[EPT];
    uint32_t cl = 0;
#pragma unroll
    for (int j = 0; j < EPT; j++) {
        int c = j * T1 + t;
        uint32_t u = __float_as_uint(row[c]);
        skey[j] = u ^ ((u & 0x80000000u) ? 0xFFFFFFFFu : 0x80000000u);
        rkey[j] = rand_key((uint32_t)(q * CC + c), m13,m15,m26,m6,m17,m29,m16,m24,m1);
        uint32_t d = skey[j] - KLO;
        if (d < FRNG) atomicAdd(&hist[d >> 11], 1u);
        if (rkey[j] < PIV) atomicAdd(&hist[4096u + (rkey[j] >> 17)], 1u);
        cl += (d >= BELOW_THR) ? 1u : 0u;
    }
    cl = __reduce_add_sync(0xFFFFFFFFu, cl);
    if (lane == 0) s_warpB[wi] = cl;
    __syncthreads();

    uint32_t hf[8], hr[8], fs = 0, rs = 0;
    {
        uint4 a0 = *(uint4*)&hist[8 * t];
        uint4 a1 = *(uint4*)&hist[8 * t + 4];
        hf[0]=a0.x; hf[1]=a0.y; hf[2]=a0.z; hf[3]=a0.w;
        hf[4]=a1.x; hf[5]=a1.y; hf[6]=a1.z; hf[7]=a1.w;
        uint4 b0 = *(uint4*)&hist[4096 + 8 * t];
        uint4 b1 = *(uint4*)&hist[4096 + 8 * t + 4];
        hr[0]=b0.x; hr[1]=b0.y; hr[2]=b0.z; hr[3]=b0.w;
        hr[4]=b1.x; hr[5]=b1.y; hr[6]=b1.z; hr[7]=b1.w;
    }
#pragma unroll
    for (int i = 0; i < 8; i++) { fs += hf[i]; rs += hr[i]; }
    uint32_t v = fs | (rs << 16);
    uint32_t incl = warp_inscan(v, lane);
    if (lane == 31) s_warpA[wi] = incl;
    if (t == 0) {
        uint32_t s = 0;
#pragma unroll
        for (int i = 0; i < 16; i++) s += s_warpB[i];
        s_cnt[0] = s;
    }
    __syncthreads();
    if (wi == 0) {
        uint32_t wv = (lane < 16) ? s_warpA[lane] : 0u;
        uint32_t wincl = warp_inscan(wv, lane);
        if (lane < 16) s_warpA[lane] = wincl - wv;
        if (lane == 15) s_cnt[1] = wincl;
    }
    __syncthreads();
    const uint32_t c_lo = s_cnt[0];
    const uint32_t n_in = s_cnt[1] & 0xFFFFu;
    const uint32_t c0   = s_cnt[1] >> 16;
    const uint32_t kfp  = K_FRONT - 1u - c_lo;
    const uint32_t krp  = K_RAND - 1u;
    {
        uint32_t base = (incl - v) + s_warpA[wi];
        uint32_t run = base & 0xFFFFu;
        if (kfp - run < fs) {
#pragma unroll
            for (int i = 0; i < 8; i++) {
                if (kfp >= run && kfp < run + hf[i]) {
                    s_ctl[0] = (uint32_t)(8 * t + i);
                    s_ctl[1] = kfp - run;
                    s_ctl[4] = hf[i];
                }
                run += hf[i];
            }
        }
        run = base >> 16;
        if (krp - run < rs) {
#pragma unroll
            for (int i = 0; i < 8; i++) {
                if (krp >= run && krp < run + hr[i]) {
                    s_ctl[2] = (uint32_t)(8 * t + i);
                    s_ctl[3] = krp - run;
                    s_ctl[5] = hr[i];
                }
                run += hr[i];
            }
        }
    }
    __syncthreads();

    uint32_t Tf, need_f, Tr, need_r, cnt_f = 0, cnt_r = 0;
    const bool fast = (c_lo <= K_FRONT - 1u) &&
                      (K_FRONT - 1u < c_lo + n_in) &&
                      (c0 >= K_RAND);
    if (!fast) {
        radix8_fallback(skey, K_FRONT, 4, t, lane, hist, s_ctl, Tf, need_f);
        radix8_fallback(rkey, K_RAND, 3, t, lane, hist, s_ctl, Tr, need_r);
    } else {
        const uint32_t Bf = s_ctl[0], kf2 = s_ctl[1], cbf = s_ctl[4];
        const uint32_t Br = s_ctl[2], kr2 = s_ctl[3], cbr = s_ctl[5];
        const bool p2f = (cbf != 1u);
        const bool p2r = (cbr != 1u);

#pragma unroll
        for (int j = 0; j < EPT; j++) {
            uint32_t d = skey[j] - KLO;
            if (d < FRNG && (d >> 11) == Bf) {
                if (p2f) atomicAdd(&hist[8192u + (d & 0x7FFu)], 1u);
                else     s_val[0] = skey[j];
            }
            if (rkey[j] < PIV && (rkey[j] >> 17) == Br) {
                if (p2r) atomicAdd(&hist[10240u + ((rkey[j] >> 9) & 0xFFu)], 1u);
                else     s_val[1] = rkey[j];
            }
        }
        __syncthreads();

        if (p2f || p2r) {
            uint32_t g2[4], f2 = 0;
            {
                uint4 c4 = *(uint4*)&hist[8192 + 4 * t];
                g2[0]=c4.x; g2[1]=c4.y; g2[2]=c4.z; g2[3]=c4.w;
            }
#pragma unroll
            for (int i = 0; i < 4; i++) f2 += g2[i];
            uint32_t r2 = (t < 256) ? hist[10240 + t] : 0u;
            uint32_t v2 = f2 | (r2 << 16);
            uint32_t incl2 = warp_inscan(v2, lane);
            if (lane == 31) s_warpA[wi] = incl2;
            __syncthreads();
            if (wi == 0) {
                uint32_t wv = (lane < 16) ? s_warpA[lane] : 0u;
                uint32_t wincl = warp_inscan(wv, lane);
                if (lane < 16) s_warpA[lane] = wincl - wv;
            }
            __syncthreads();
            uint32_t base2 = (incl2 - v2) + s_warpA[wi];
            if (p2f) {
                uint32_t run = base2 & 0xFFFFu;
                if (kf2 - run < f2) {
#pragma unroll
                    for (int i = 0; i < 4; i++) {
                        if (kf2 >= run && kf2 < run + g2[i]) {
                            s_ctl[0] = (uint32_t)(4 * t + i);
                            s_ctl[1] = kf2 - run;
                            s_ctl[4] = g2[i];
                        }
                        run += g2[i];
                    }
                }
            }
            if (p2r && t < 256) {
                uint32_t run = base2 >> 16;
                if (kr2 >= run && kr2 < run + r2) {
                    s_ctl[2] = (uint32_t)t;
                    s_ctl[3] = kr2 - run;
                    s_ctl[5] = r2;
                }
            }
        }
        __syncthreads();
        if (p2f) { Tf = KLO + (Bf << 11) + s_ctl[0]; need_f = s_ctl[1] + 1u; cnt_f = s_ctl[4]; }
        else     { Tf = s_val[0];                    need_f = 1u;            cnt_f = 1u; }
        if (p2r) { Tr = (Br << 17) + (s_ctl[2] << 9); need_r = s_ctl[3] + 1u; cnt_r = s_ctl[5]; }
        else     { Tr = s_val[1];                     need_r = 1u;            cnt_r = 1u; }
    }

    const bool is_row0 = ((q & (RR - 1)) == 0);
    const bool easy = (cnt_f == need_f) && (cnt_r == need_r);
    if (easy) {
#pragma unroll
        for (int j = 0; j < EPT; j++) {
            const int w = j * 16 + wi;
            bool fsel = skey[j] <= Tf;
            bool sel  = fsel || (rkey[j] <= Tr);
            uint32_t keep_w = __ballot_sync(0xFFFFFFFFu, !sel);
            if (lane == 0) g_smask[q * WORDS + w] = keep_w;
            if (is_row0) {
                uint32_t front_w = __ballot_sync(0xFFFFFFFFu, fsel);
                if (lane == 0) g_front0[(q >> 11) * WORDS + w] = front_w;
            }
        }
    } else {
        __syncthreads();
#pragma unroll
        for (int j = 0; j < EPT; j++) {
            uint32_t bfw = __ballot_sync(0xFFFFFFFFu, skey[j] == Tf);
            uint32_t brw = __ballot_sync(0xFFFFFFFFu, rkey[j] == Tr);
            if (lane == 0) { s_bf[j * 16 + wi] = bfw; s_br[j * 16 + wi] = brw; }
        }
        __syncthreads();
        if (t < 32) {
            uint32_t a[4], b[4], sa = 0, sb = 0;
#pragma unroll
            for (int i = 0; i < 4; i++) { a[i] = __popc(s_bf[4 * t + i]); sa += a[i];
                                          b[i] = __popc(s_br[4 * t + i]); sb += b[i]; }
            uint32_t ea = warp_exscan(sa, t), eb = warp_exscan(sb, t);
#pragma unroll
            for (int i = 0; i < 4; i++) {
                s_pf[4 * t + i] = ea; ea += a[i];
                s_pr[4 * t + i] = eb; eb += b[i];
            }
        }
        __syncthreads();
#pragma unroll
        for (int j = 0; j < EPT; j++) {
            const int w = j * 16 + wi;
            uint32_t bfw = s_bf[w], brw = s_br[w];
            bool fsel = (skey[j] < Tf) ||
                        ((skey[j] == Tf) && (s_pf[w] + __popc(bfw & lmask_lt) < need_f));
            bool rsel = (rkey[j] < Tr) ||
                        ((rkey[j] == Tr) && (s_pr[w] + __popc(brw & lmask_lt) < need_r));
            uint32_t keep_w  = __ballot_sync(0xFFFFFFFFu, !(fsel || rsel));
            uint32_t front_w = __ballot_sync(0xFFFFFFFFu, fsel);
            if (lane == 0) {
                g_smask[q * WORDS + w] = keep_w;
                if (is_row0) g_front0[(q >> 11) * WORDS + w] = front_w;
            }
        }
    }
}

// ============================================================================
// Kernel 2 (chunked by batch b): masked transpose tile, streaming ld/st.
// ============================================================================
#define TJ 128
#define TM 32
__global__ __launch_bounds__(256) void k2_transpose(const float* __restrict__ score,
                                                    float* __restrict__ out_s,
                                                    float* __restrict__ out_t,
                                                    int b) {
    __shared__ float ss[TM * TJ];
    __shared__ float st[TM * TJ];
    const int m0 = blockIdx.y * TM;
    const int j0 = blockIdx.x * TJ;
    const int t  = threadIdx.x;
    const int lane = t & 31, wid = t >> 5;

    const float* base = score + (size_t)b * (RR * CC);
#pragma unroll
    for (int k = 0; k < 4; k++) {
        const int mr = wid + 8 * k;
        const int m  = m0 + mr;
        const int j  = 4 * lane;
        const float4 v = __ldcs((const float4*)(base + (size_t)m * 2048 + j0 + j));
        const int r = m >> 1;
        const int c = ((m & 1) << 11) + j0 + j;
        const uint32_t sh = c & 31;
        const uint32_t mw = g_smask[(b * RR + r) * WORDS + (c >> 5)];
        float4 vs;
        vs.x = ((mw >> (sh + 0)) & 1u) ? v.x : 0.0f;
        vs.y = ((mw >> (sh + 1)) & 1u) ? v.y : 0.0f;
        vs.z = ((mw >> (sh + 2)) & 1u) ? v.z : 0.0f;
        vs.w = ((mw >> (sh + 3)) & 1u) ? v.w : 0.0f;
        float4 vt = v;
        if (r == 0) {
            const uint32_t fw = g_front0[b * WORDS + (c >> 5)];
            vt.x = ((fw >> (sh + 0)) & 1u) ? v.x : 0.0f;
            vt.y = ((fw >> (sh + 1)) & 1u) ? v.y : 0.0f;
            vt.z = ((fw >> (sh + 2)) & 1u) ? v.z : 0.0f;
            vt.w = ((fw >> (sh + 3)) & 1u) ? v.w : 0.0f;
        }
        const int col4 = lane ^ ((mr >> 2) & 7);
        *(float4*)&ss[mr * TJ + 4 * col4] = vs;
        *(float4*)&st[mr * TJ + 4 * col4] = vt;
    }
    __syncthreads();

    float* os = out_s + (size_t)b * (RR * CC);
    float* ot = out_t + (size_t)b * (RR * CC);
    const int qd = t & 7;
#pragma unroll
    for (int jj = 0; jj < 4; jj++) {
        const int jl = (t >> 3) + 32 * jj;
        const int cw = 4 * ((jl >> 2) ^ qd) + (jl & 3);
        float4 rs, rt;
        rs.x = ss[(4 * qd + 0) * TJ + cw];
        rs.y = ss[(4 * qd + 1) * TJ + cw];
        rs.z = ss[(4 * qd + 2) * TJ + cw];
        rs.w = ss[(4 * qd + 3) * TJ + cw];
        rt.x = st[(4 * qd + 0) * TJ + cw];
        rt.y = st[(4 * qd + 1) * TJ + cw];
        rt.z = st[(4 * qd + 2) * TJ + cw];
        rt.w = st[(4 * qd + 3) * TJ + cw];
        const size_t o = (size_t)(j0 + jl) * CC + m0 + 4 * qd;
        __stwt((float4*)(os + o), rs);
        __stwt((float4*)(ot + o), rt);
    }
}

// ============================================================================
// Launch: per-batch software pipeline across two streams. k1 chunk b fills
// masks for batch b and records ev[b]; k2 chunk b (side stream) waits on
// ev[b], so it overlaps with k1 chunks b+1.. . Joined back before return.
// ============================================================================
extern "C" void kernel_launch(void* const* d_in, const int* in_sizes, int n_in,
                              void* d_out, int out_size) {
    const float* score = (const float*)d_in[0];
    float* out = (float*)d_out;
    float* out_teacher = out + (size_t)BB * RR * CC;

    // Host-side resources, created once (no device memory involved).
    static cudaStream_t s1 = nullptr;
    static cudaEvent_t ev[BB], ev_join;
    if (s1 == nullptr) {
        cudaStreamCreateWithFlags(&s1, cudaStreamNonBlocking);
        for (int b = 0; b < BB; b++)
            cudaEventCreateWithFlags(&ev[b], cudaEventDisableTiming);
        cudaEventCreateWithFlags(&ev_join, cudaEventDisableTiming);
    }

    for (int b = 0; b < BB; b++) {
        k1_select<<<RR, T1>>>(score, b * RR,
            1u << 13, 1u << 15, 1u << 26, 1u << 6,
            1u << 17, 1u << 29, 1u << 16, 1u << 24, 1u);
        cudaEventRecord(ev[b], 0);
    }
    dim3 grid(CC / 2 / TJ, CC / TM, 1);   // (16, 128)
    for (int b = 0; b < BB; b++) {
        cudaStreamWaitEvent(s1, ev[b], 0);
        k2_transpose<<<grid, 256, 0, s1>>>(score, out, out_teacher, b);
    }
    cudaEventRecord(ev_join, s1);
    cudaStreamWaitEvent(0, ev_join, 0);   // join side stream back into capture
    noop_kernel<<<1, 1>>>();
}